// round 12
// baseline (speedup 1.0000x reference)
#include <cuda_runtime.h>
#include <math.h>
#include <cstdint>

#define B_   2
#define T_   2048
#define C_   4096
#define H_   32
#define KVH_ 8
#define HS_  128
#define GROUPS (H_/KVH_)
#define GK    4096

// ---------------------------------------------------------------------------
// Scratch
// ---------------------------------------------------------------------------
__device__ float g_Q[(size_t)B_*T_*H_*HS_];      // d-permuted after postproc
__device__ float g_K[(size_t)B_*T_*KVH_*HS_];    // d-permuted after postproc
__device__ float g_V[(size_t)B_*T_*KVH_*HS_];    // raw from gemm
__device__ float g_Vt[(size_t)B_*KVH_*HS_*T_];   // V^T, t-permuted, tf32
__device__ float g_Y[(size_t)B_*T_*H_*HS_];      // tf32-rounded (unpermuted)
__device__ float g_WqT[(size_t)C_*H_*HS_];       // [N][K], K k-permuted, tf32
__device__ float g_WkT[(size_t)C_*KVH_*HS_];
__device__ float g_WvT[(size_t)C_*KVH_*HS_];
__device__ float g_WoT[(size_t)H_*HS_*C_];

// ---------------------------------------------------------------------------
// Helpers
// ---------------------------------------------------------------------------
__device__ __forceinline__ uint32_t smem_to_u32(const void* p) {
    uint32_t a;
    asm("{ .reg .u64 t; cvta.to.shared.u64 t, %1; cvt.u32.u64 %0, t; }" : "=r"(a) : "l"(p));
    return a;
}
__device__ __forceinline__ uint32_t f2tf32(float x) {
    uint32_t u;
    asm("cvt.rna.tf32.f32 %0, %1;" : "=r"(u) : "f"(x));
    return u;
}
__device__ __forceinline__ float rndf(float x) { return __uint_as_float(f2tf32(x)); }

__device__ __forceinline__ void cp_async16(uint32_t smem_addr, const void* gptr) {
    asm volatile("cp.async.cg.shared.global [%0], [%1], 16;" :: "r"(smem_addr), "l"(gptr));
}
#define CP_COMMIT() asm volatile("cp.async.commit_group;" ::: "memory")
#define CP_WAIT(n)  asm volatile("cp.async.wait_group %0;" :: "n"(n) : "memory")

__device__ __forceinline__ void mma_tf32(
    float& d0, float& d1, float& d2, float& d3,
    uint32_t a0, uint32_t a1, uint32_t a2, uint32_t a3,
    uint32_t b0, uint32_t b1)
{
    asm volatile(
        "mma.sync.aligned.m16n8k8.row.col.f32.tf32.tf32.f32 "
        "{%0,%1,%2,%3}, {%4,%5,%6,%7}, {%8,%9}, {%0,%1,%2,%3};"
        : "+f"(d0), "+f"(d1), "+f"(d2), "+f"(d3)
        : "r"(a0), "r"(a1), "r"(a2), "r"(a3), "r"(b0), "r"(b1));
}

// ---------------------------------------------------------------------------
// Launch 1: weight transposes (float4 loads + float4 gather-stores),
// tf32-round + k-pair-permute the K dimension.
// ---------------------------------------------------------------------------
__global__ __launch_bounds__(256) void prep_kernel(
    const float* __restrict__ Wq, const float* __restrict__ Wk,
    const float* __restrict__ Wv, const float* __restrict__ Wo,
    float* __restrict__ wqT, float* __restrict__ wkT,
    float* __restrict__ wvT, float* __restrict__ woT)
{
    __shared__ float tile[32 * 33];
    int z = blockIdx.z;
    int tid = threadIdx.x;
    const float* src; float* dst; int rows, cols;
    if (z == 0)      { src = Wq; dst = wqT; rows = 4096; cols = 4096; }
    else if (z == 1) { src = Wk; dst = wkT; rows = 4096; cols = 1024; if (blockIdx.x >= 32) return; }
    else if (z == 2) { src = Wv; dst = wvT; rows = 4096; cols = 1024; if (blockIdx.x >= 32) return; }
    else             { src = Wo; dst = woT; rows = 4096; cols = 4096; }
    int c0 = blockIdx.x * 32, r0 = blockIdx.y * 32;

    // load: float4 from global, scalar stores into 33-stride tile
    {
        int row = tid >> 3, c4 = (tid & 7) * 4;
        float4 v = *(const float4*)(src + (size_t)(r0 + row) * cols + c0 + c4);
        tile[row * 33 + c4 + 0] = v.x;
        tile[row * 33 + c4 + 1] = v.y;
        tile[row * 33 + c4 + 2] = v.z;
        tile[row * 33 + c4 + 3] = v.w;
    }
    __syncthreads();

    // store: gather 4 permuted k-positions, round, float4 store
    {
        int y = tid >> 3, j4 = tid & 7;
        int pbase = j4 * 4;
        int blk = pbase & ~7;
        float4 w;
        #pragma unroll
        for (int i = 0; i < 4; i++) {
            int q = (pbase + i) & 7;
            int o = blk + ((q & 1) ? (q >> 1) + 4 : (q >> 1));
            ((float*)&w)[i] = rndf(tile[o * 33 + y]);
        }
        *(float4*)(dst + (size_t)(c0 + y) * rows + r0 + pbase) = w;
    }
}

// ---------------------------------------------------------------------------
// tf32 mma.sync GEMM core: 128x128 tile, 256 threads, 2 CTAs/SM.
// A staged RAW (SA_A=36, scalar frags + cvt.rna); B permuted tf32 (SA_B=40,
// LDS.64 frags). Double-buffered cp.async, single sync per k-tile.
// ---------------------------------------------------------------------------
#define SAA       36
#define SAB       40
#define A_FLT     (128 * SAA)
#define STAGE_FLT (128 * SAA + 128 * SAB)      // 9728
#define GEMM_SMEM (2 * STAGE_FLT * 4)          // 77824
#define KTILES    (GK / 32)

__device__ __forceinline__ void gemm_core(
    int N, const float* __restrict__ A, const float* __restrict__ BT,
    const float* __restrict__ bias, float* __restrict__ C,
    int m0, int n0, float* sm)
{
    uint32_t sb = smem_to_u32(sm);
    int tid  = threadIdx.x;
    int lane = tid & 31, wid = tid >> 5;
    int wr = wid >> 2, wc = wid & 3;
    int g  = lane >> 2, tg = lane & 3;
    int ldRow = tid >> 3;
    int ldC4  = (tid & 7) * 4;

    float acc[4][4][4];
    #pragma unroll
    for (int i = 0; i < 4; i++)
        #pragma unroll
        for (int j = 0; j < 4; j++)
            #pragma unroll
            for (int k = 0; k < 4; k++) acc[i][j][k] = 0.f;

    auto issue_tile = [&](int kt, int s) {
        const float* Ag = A  + (size_t)(m0) * GK + kt * 32;
        const float* Bg = BT + (size_t)(n0) * GK + kt * 32;
        uint32_t stA = sb + (uint32_t)(s * STAGE_FLT) * 4;
        uint32_t stB = stA + (uint32_t)A_FLT * 4;
        #pragma unroll
        for (int i = 0; i < 4; i++) {
            int row = ldRow + 32 * i;
            cp_async16(stA + (uint32_t)(row * SAA + ldC4) * 4,
                       Ag + (size_t)row * GK + ldC4);
            cp_async16(stB + (uint32_t)(row * SAB + ldC4) * 4,
                       Bg + (size_t)row * GK + ldC4);
        }
    };

    issue_tile(0, 0);
    CP_COMMIT();

    for (int kt = 0; kt < KTILES; kt++) {
        int s = kt & 1;
        CP_WAIT(0);
        __syncthreads();
        if (kt + 1 < KTILES) { issue_tile(kt + 1, s ^ 1); CP_COMMIT(); }

        const float* As = sm + s * STAGE_FLT;
        const float* Bs = As + A_FLT;

        #pragma unroll
        for (int ks = 0; ks < 4; ks++) {
            int kc = ks * 8 + tg;          // orig k (raw A layout)
            int kb = ks * 8 + 2 * tg;      // permuted pair position (B layout)
            uint32_t bfr[4][2];
            #pragma unroll
            for (int nt = 0; nt < 4; nt++) {
                float2 lb = *(const float2*)(Bs + (wc * 32 + nt * 8 + g) * SAB + kb);
                bfr[nt][0] = __float_as_uint(lb.x);
                bfr[nt][1] = __float_as_uint(lb.y);
            }
            #pragma unroll
            for (int mt = 0; mt < 4; mt++) {
                int ar0 = wr * 64 + mt * 16 + g;
                uint32_t a0 = f2tf32(As[ar0 * SAA + kc]);
                uint32_t a1 = f2tf32(As[(ar0 + 8) * SAA + kc]);
                uint32_t a2 = f2tf32(As[ar0 * SAA + kc + 4]);
                uint32_t a3 = f2tf32(As[(ar0 + 8) * SAA + kc + 4]);
                #pragma unroll
                for (int nt = 0; nt < 4; nt++)
                    mma_tf32(acc[mt][nt][0], acc[mt][nt][1], acc[mt][nt][2], acc[mt][nt][3],
                             a0, a1, a2, a3, bfr[nt][0], bfr[nt][1]);
            }
        }
    }

    #pragma unroll
    for (int mt = 0; mt < 4; mt++) {
        int r0 = m0 + wr * 64 + mt * 16 + g;
        #pragma unroll
        for (int nt = 0; nt < 4; nt++) {
            int cc = n0 + wc * 32 + nt * 8 + 2 * tg;
            float2 bv = *(const float2*)(bias + cc);
            float2 o0, o1;
            o0.x = acc[mt][nt][0] + bv.x;
            o0.y = acc[mt][nt][1] + bv.y;
            o1.x = acc[mt][nt][2] + bv.x;
            o1.y = acc[mt][nt][3] + bv.y;
            *(float2*)(C + (size_t)r0 * N + cc)       = o0;
            *(float2*)(C + (size_t)(r0 + 8) * N + cc) = o1;
        }
    }
}

// Launch 2: fused Q+K+V projections (grid.x = 48); A = raw inputs
__global__ __launch_bounds__(256, 2) void mma_gemm_qkv(
    const float* __restrict__ Aq, const float* __restrict__ Akv,
    const float* __restrict__ BTq, const float* __restrict__ BTk, const float* __restrict__ BTv,
    const float* __restrict__ bq, const float* __restrict__ bk, const float* __restrict__ bv,
    float* __restrict__ Cq, float* __restrict__ Ck, float* __restrict__ Cv)
{
    extern __shared__ float sm[];
    int bx = blockIdx.x, by = blockIdx.y;
    if (bx < 32)      gemm_core(4096, Aq,  BTq, bq, Cq, by * 128, bx * 128, sm);
    else if (bx < 40) gemm_core(1024, Akv, BTk, bk, Ck, by * 128, (bx - 32) * 128, sm);
    else              gemm_core(1024, Akv, BTv, bv, Cv, by * 128, (bx - 40) * 128, sm);
}

// Launch 6: O projection; A = g_Y (already tf32-rounded; cvt is identity)
__global__ __launch_bounds__(256, 2) void mma_gemm_bias(
    int N, const float* __restrict__ A, const float* __restrict__ BT,
    const float* __restrict__ bias, float* __restrict__ C)
{
    extern __shared__ float sm[];
    gemm_core(N, A, BT, bias, C, blockIdx.y * 128, blockIdx.x * 128, sm);
}

// ---------------------------------------------------------------------------
// Launch 3: RoPE(Q,K) + tf32-round + d-pair-permute (in-place safe).
// ---------------------------------------------------------------------------
#define QROWS (B_*T_*H_)      // 131072
#define KROWS (B_*T_*KVH_)    // 32768
#define LOG2_10000_D64 0.20762050593048358f
__global__ void postproc(float* __restrict__ Q, float* __restrict__ K)
{
    long i = (long)blockIdx.x * blockDim.x + threadIdx.x;
    float* X; int hshift; long idx;
    if (i < (long)QROWS * 8) { X = Q; hshift = 5; idx = i; }
    else                     { X = K; hshift = 3; idx = i - (long)QROWS * 8; }
    int j0 = (int)(idx & 7);
    long rh = idx >> 3;
    long row = rh >> hshift;
    int t = (int)(row & (T_ - 1));

    float* p = X + rh * HS_ + j0 * 8;
    float lo[8], hi[8], ol[8], oh[8];
    *(float4*)(lo)     = *(const float4*)(p);
    *(float4*)(lo + 4) = *(const float4*)(p + 4);
    *(float4*)(hi)     = *(const float4*)(p + 64);
    *(float4*)(hi + 4) = *(const float4*)(p + 68);
    #pragma unroll
    for (int jj = 0; jj < 8; jj++) {
        int d = j0 * 8 + jj;
        float inv = exp2f(-(float)d * LOG2_10000_D64);
        float ang = (float)t * inv;
        float c = cosf(ang), s = sinf(ang);
        ol[jj] = rndf(lo[jj] * c - hi[jj] * s);
        oh[jj] = rndf(hi[jj] * c + lo[jj] * s);
    }
    float4 w0, w1;
    w0.x = ol[0]; w0.y = ol[4]; w0.z = ol[1]; w0.w = ol[5];
    w1.x = ol[2]; w1.y = ol[6]; w1.z = ol[3]; w1.w = ol[7];
    *(float4*)(p)     = w0;
    *(float4*)(p + 4) = w1;
    w0.x = oh[0]; w0.y = oh[4]; w0.z = oh[1]; w0.w = oh[5];
    w1.x = oh[2]; w1.y = oh[6]; w1.z = oh[3]; w1.w = oh[7];
    *(float4*)(p + 64) = w0;
    *(float4*)(p + 68) = w1;
}

// ---------------------------------------------------------------------------
// Launch 4: V transpose -> Vt[b][kh][d][t], tf32-rounded, t-pair-permuted.
// ---------------------------------------------------------------------------
__global__ void vtrans_kernel(const float* __restrict__ V, float* __restrict__ Vt)
{
    __shared__ float tile[32][33];
    int z = blockIdx.z;
    int b = z >> 3, kh = z & 7;
    int t0 = blockIdx.x * 32, d0 = blockIdx.y * 32;
    int x = threadIdx.x, y0 = threadIdx.y;
    #pragma unroll
    for (int y = y0; y < 32; y += 8)
        tile[y][x] = V[((size_t)(b * T_ + t0 + y) * KVH_ + kh) * HS_ + d0 + x];
    __syncthreads();
    int jb = x & 7;
    int px = (x & ~7) + ((jb < 4) ? 2 * jb : 2 * (jb - 4) + 1);
    #pragma unroll
    for (int y = y0; y < 32; y += 8)
        Vt[((size_t)z * HS_ + d0 + y) * T_ + t0 + px] = rndf(tile[x][y]);
}

// ---------------------------------------------------------------------------
// Launch 5: tensor-core causal flash attention.
// exp2-domain softmax; P via register shuffles; single sync per tile.
// Y stored unpermuted (tf32-rounded).
// ---------------------------------------------------------------------------
#define KS 136
#define VS 72
#define OFF_KS0 0
#define OFF_KS1 8704
#define OFF_VS0 17408
#define OFF_VS1 26624
#define ATTN_SMEM (35840 * 4)

__global__ __launch_bounds__(256) void attn_mma(
    const float* __restrict__ Q, const float* __restrict__ K,
    const float* __restrict__ Vt, float* __restrict__ Y)
{
    extern __shared__ float sm[];
    uint32_t sb = smem_to_u32(sm);
    int tid = threadIdx.x, lane = tid & 31, w = tid >> 5;
    int g = lane >> 2, tg = lane & 3;
    int qb = gridDim.x - 1 - blockIdx.x;
    int h = blockIdx.y, b = blockIdx.z;
    int kh = h / GROUPS;
    const float scale_l2e = 0.08838834764831845f * 1.4426950408889634f;
    int r0 = qb * 128 + w * 16 + g;

    for (int i = tid; i < 128 * 32; i += 256) {
        int row = i >> 5, c4 = (i & 31) * 4;
        *(float4*)(sm + row * KS + c4) =
            *(const float4*)(Q + (size_t)(b * T_ + qb * 128 + row) * (H_ * HS_) + h * HS_ + c4);
    }
    __syncthreads();
    uint32_t qf[16][4];
    #pragma unroll
    for (int ks = 0; ks < 16; ks++) {
        int kb = ks * 8 + 2 * tg;
        float2 q0 = *(const float2*)(sm + (w * 16 + g)     * KS + kb);
        float2 q1 = *(const float2*)(sm + (w * 16 + g + 8) * KS + kb);
        qf[ks][0] = f2tf32(q0.x * scale_l2e);
        qf[ks][1] = f2tf32(q1.x * scale_l2e);
        qf[ks][2] = f2tf32(q0.y * scale_l2e);
        qf[ks][3] = f2tf32(q1.y * scale_l2e);
    }
    __syncthreads();

    float O[16][4];
    #pragma unroll
    for (int i = 0; i < 16; i++)
        #pragma unroll
        for (int j = 0; j < 4; j++) O[i][j] = 0.f;
    float m0 = -1e30f, m1 = -1e30f, l0 = 0.f, l1 = 0.f;

    int nt = 2 * qb + 2;

    auto issue_kv = [&](int jt, int s) {
        uint32_t kbase = sb + (uint32_t)(s ? OFF_KS1 : OFF_KS0) * 4;
        uint32_t vbase = sb + (uint32_t)(s ? OFF_VS1 : OFF_VS0) * 4;
        const float* Kg  = K + ((size_t)(b * T_ + jt * 64) * KVH_ + kh) * HS_;
        const float* Vg  = Vt + ((size_t)(b * KVH_ + kh) * HS_) * T_ + jt * 64;
        #pragma unroll
        for (int j = 0; j < 8; j++) {
            int ii = tid + 256 * j;
            int krow = ii >> 5, kc4 = (ii & 31) * 4;
            cp_async16(kbase + (uint32_t)(krow * KS + kc4) * 4,
                       Kg + (size_t)krow * (KVH_ * HS_) + kc4);
            int vrow = ii >> 4, vc4 = (ii & 15) * 4;
            cp_async16(vbase + (uint32_t)(vrow * VS + vc4) * 4,
                       Vg + (size_t)vrow * T_ + vc4);
        }
    };

    issue_kv(0, 0);
    CP_COMMIT();

    for (int jt = 0; jt < nt; jt++) {
        int s = jt & 1;
        CP_WAIT(0);
        __syncthreads();
        if (jt + 1 < nt) { issue_kv(jt + 1, s ^ 1); CP_COMMIT(); }

        const float* Ksm = sm + (s ? OFF_KS1 : OFF_KS0);
        const float* Vsm = sm + (s ? OFF_VS1 : OFF_VS0);

        float S[8][4];
        #pragma unroll
        for (int i = 0; i < 8; i++)
            #pragma unroll
            for (int j = 0; j < 4; j++) S[i][j] = 0.f;

        #pragma unroll
        for (int ks = 0; ks < 16; ks++) {
            int kb = ks * 8 + 2 * tg;
            #pragma unroll
            for (int nf = 0; nf < 8; nf++) {
                float2 lb = *(const float2*)(Ksm + (nf * 8 + g) * KS + kb);
                mma_tf32(S[nf][0], S[nf][1], S[nf][2], S[nf][3],
                         qf[ks][0], qf[ks][1], qf[ks][2], qf[ks][3],
                         __float_as_uint(lb.x), __float_as_uint(lb.y));
            }
        }

        if (jt >= 2 * qb) {
            int cb = jt * 64;
            #pragma unroll
            for (int nf = 0; nf < 8; nf++) {
                int c0 = cb + nf * 8 + 2 * tg, c1 = c0 + 1;
                if (c0 > r0)     S[nf][0] = -1e30f;
                if (c1 > r0)     S[nf][1] = -1e30f;
                if (c0 > r0 + 8) S[nf][2] = -1e30f;
                if (c1 > r0 + 8) S[nf][3] = -1e30f;
            }
        }

        float mx0 = -1e30f, mx1 = -1e30f;
        #pragma unroll
        for (int nf = 0; nf < 8; nf++) {
            mx0 = fmaxf(mx0, fmaxf(S[nf][0], S[nf][1]));
            mx1 = fmaxf(mx1, fmaxf(S[nf][2], S[nf][3]));
        }
        mx0 = fmaxf(mx0, __shfl_xor_sync(0xffffffffu, mx0, 1));
        mx0 = fmaxf(mx0, __shfl_xor_sync(0xffffffffu, mx0, 2));
        mx1 = fmaxf(mx1, __shfl_xor_sync(0xffffffffu, mx1, 1));
        mx1 = fmaxf(mx1, __shfl_xor_sync(0xffffffffu, mx1, 2));

        float mn0 = fmaxf(m0, mx0), mn1 = fmaxf(m1, mx1);
        float a0 = exp2f(m0 - mn0), a1 = exp2f(m1 - mn1);
        float s0 = 0.f, s1 = 0.f;
        #pragma unroll
        for (int nf = 0; nf < 8; nf++) {
            S[nf][0] = exp2f(S[nf][0] - mn0);
            S[nf][1] = exp2f(S[nf][1] - mn0);
            S[nf][2] = exp2f(S[nf][2] - mn1);
            S[nf][3] = exp2f(S[nf][3] - mn1);
            s0 += S[nf][0] + S[nf][1];
            s1 += S[nf][2] + S[nf][3];
        }
        s0 += __shfl_xor_sync(0xffffffffu, s0, 1);
        s0 += __shfl_xor_sync(0xffffffffu, s0, 2);
        s1 += __shfl_xor_sync(0xffffffffu, s1, 1);
        s1 += __shfl_xor_sync(0xffffffffu, s1, 2);
        l0 = l0 * a0 + s0; l1 = l1 * a1 + s1;
        m0 = mn0; m1 = mn1;

        #pragma unroll
        for (int nf2 = 0; nf2 < 16; nf2++) {
            O[nf2][0] *= a0; O[nf2][1] *= a0;
            O[nf2][2] *= a1; O[nf2][3] *= a1;
        }

        int src0 = (lane & 28) | (tg >> 1);
        int src1 = src0 + 2;
        #pragma unroll
        for (int kb2 = 0; kb2 < 8; kb2++) {
            float p00 = __shfl_sync(0xffffffffu, S[kb2][0], src0);
            float p01 = __shfl_sync(0xffffffffu, S[kb2][1], src0);
            float p10 = __shfl_sync(0xffffffffu, S[kb2][2], src0);
            float p11 = __shfl_sync(0xffffffffu, S[kb2][3], src0);
            float r00 = __shfl_sync(0xffffffffu, S[kb2][0], src1);
            float r01 = __shfl_sync(0xffffffffu, S[kb2][1], src1);
            float r10 = __shfl_sync(0xffffffffu, S[kb2][2], src1);
            float r11 = __shfl_sync(0xffffffffu, S[kb2][3], src1);
            int odd = tg & 1;
            uint32_t pa0 = f2tf32(odd ? p01 : p00);
            uint32_t pa1 = f2tf32(odd ? p11 : p10);
            uint32_t pa2 = f2tf32(odd ? r01 : r00);
            uint32_t pa3 = f2tf32(odd ? r11 : r10);
            int vb_off = kb2 * 8 + 2 * tg;
            #pragma unroll
            for (int nf2 = 0; nf2 < 16; nf2++) {
                float2 vb = *(const float2*)(Vsm + (nf2 * 8 + g) * VS + vb_off);
                mma_tf32(O[nf2][0], O[nf2][1], O[nf2][2], O[nf2][3],
                         pa0, pa1, pa2, pa3,
                         __float_as_uint(vb.x), __float_as_uint(vb.y));
            }
        }
    }

    // ---- epilogue: normalize, tf32-round, store UNPERMUTED (float2) ----
    float il0 = 1.f / l0, il1 = 1.f / l1;
    size_t base0 = (size_t)(b * T_ + r0) * (H_ * HS_) + h * HS_;
    size_t base1 = base0 + (size_t)8 * (H_ * HS_);
    #pragma unroll
    for (int nf2 = 0; nf2 < 16; nf2++) {
        *(float2*)(Y + base0 + nf2 * 8 + 2 * tg) =
            make_float2(rndf(O[nf2][0] * il0), rndf(O[nf2][1] * il0));
        *(float2*)(Y + base1 + nf2 * 8 + 2 * tg) =
            make_float2(rndf(O[nf2][2] * il1), rndf(O[nf2][3] * il1));
    }
}

// ---------------------------------------------------------------------------
extern "C" void kernel_launch(void* const* d_in, const int* in_sizes, int n_in,
                              void* d_out, int out_size)
{
    const float* q_x  = (const float*)d_in[0];
    const float* kv_x = (const float*)d_in[1];
    const float* Wq   = (const float*)d_in[2];
    const float* bq   = (const float*)d_in[3];
    const float* Wk   = (const float*)d_in[4];
    const float* bk   = (const float*)d_in[5];
    const float* Wv   = (const float*)d_in[6];
    const float* bv   = (const float*)d_in[7];
    const float* Wo   = (const float*)d_in[8];
    const float* bo   = (const float*)d_in[9];
    float* out = (float*)d_out;

    float *qp, *kp, *vp, *vtp, *yp, *wqT, *wkT, *wvT, *woT;
    cudaGetSymbolAddress((void**)&qp, g_Q);
    cudaGetSymbolAddress((void**)&kp, g_K);
    cudaGetSymbolAddress((void**)&vp, g_V);
    cudaGetSymbolAddress((void**)&vtp, g_Vt);
    cudaGetSymbolAddress((void**)&yp, g_Y);
    cudaGetSymbolAddress((void**)&wqT, g_WqT);
    cudaGetSymbolAddress((void**)&wkT, g_WkT);
    cudaGetSymbolAddress((void**)&wvT, g_WvT);
    cudaGetSymbolAddress((void**)&woT, g_WoT);

    const int M = B_ * T_;

    cudaFuncSetAttribute(mma_gemm_qkv, cudaFuncAttributeMaxDynamicSharedMemorySize, GEMM_SMEM);
    cudaFuncSetAttribute(mma_gemm_bias, cudaFuncAttributeMaxDynamicSharedMemorySize, GEMM_SMEM);
    cudaFuncSetAttribute(attn_mma, cudaFuncAttributeMaxDynamicSharedMemorySize, ATTN_SMEM);

    // 1. weight transposes (tf32 + k-permute)
    prep_kernel<<<dim3(128, 128, 4), 256>>>(Wq, Wk, Wv, Wo, wqT, wkT, wvT, woT);
    // 2. fused Q+K+V projections (A = raw inputs, cvt in-kernel)
    mma_gemm_qkv<<<dim3(48, M / 128), 256, GEMM_SMEM>>>(q_x, kv_x, wqT, wkT, wvT,
                                                        bq, bk, bv, qp, kp, vp);
    // 3. RoPE(Q,K)
    postproc<<<(unsigned)(((long)(QROWS + KROWS) * 8) / 256), 256>>>(qp, kp);
    // 4. V transpose
    vtrans_kernel<<<dim3(T_ / 32, HS_ / 32, B_ * KVH_), dim3(32, 8)>>>(vp, vtp);
    // 5. attention
    attn_mma<<<dim3(T_ / 128, H_, B_), 256, ATTN_SMEM>>>(qp, kp, vtp, yp);
    // 6. output projection (A = g_Y, cvt identity)
    mma_gemm_bias<<<dim3(C_ / 128, M / 128), 256, GEMM_SMEM>>>(C_, yp, woT, bo, out);
}

// round 13
// speedup vs baseline: 1.1489x; 1.1489x over previous
#include <cuda_runtime.h>
#include <math.h>
#include <cstdint>

#define B_   2
#define T_   2048
#define C_   4096
#define H_   32
#define KVH_ 8
#define HS_  128
#define GROUPS (H_/KVH_)
#define GK    4096

// ---------------------------------------------------------------------------
// Scratch
// ---------------------------------------------------------------------------
__device__ float g_Q[(size_t)B_*T_*H_*HS_];      // d-permuted after fixup
__device__ float g_K[(size_t)B_*T_*KVH_*HS_];    // d-permuted after fixup
__device__ float g_V[(size_t)B_*T_*KVH_*HS_];    // raw from gemm
__device__ float g_Vt[(size_t)B_*KVH_*HS_*T_];   // V^T, t-permuted, tf32
__device__ float g_Y[(size_t)B_*T_*H_*HS_];      // k-permuted layout
__device__ float g_WqT[(size_t)C_*H_*HS_];       // [N][K], K k-permuted
__device__ float g_WkT[(size_t)C_*KVH_*HS_];
__device__ float g_WvT[(size_t)C_*KVH_*HS_];
__device__ float g_WoT[(size_t)H_*HS_*C_];
__device__ float g_Xq[(size_t)B_*T_*C_];         // tf32-rounded + k-permuted
__device__ float g_Xkv[(size_t)B_*T_*C_];

// ---------------------------------------------------------------------------
// Helpers
// ---------------------------------------------------------------------------
__device__ __forceinline__ uint32_t smem_to_u32(const void* p) {
    uint32_t a;
    asm("{ .reg .u64 t; cvta.to.shared.u64 t, %1; cvt.u32.u64 %0, t; }" : "=r"(a) : "l"(p));
    return a;
}
__device__ __forceinline__ uint32_t f2tf32(float x) {
    uint32_t u;
    asm("cvt.rna.tf32.f32 %0, %1;" : "=r"(u) : "f"(x));
    return u;
}
__device__ __forceinline__ float rndf(float x) { return __uint_as_float(f2tf32(x)); }

__device__ __forceinline__ void cp_async16(uint32_t smem_addr, const void* gptr) {
    asm volatile("cp.async.cg.shared.global [%0], [%1], 16;" :: "r"(smem_addr), "l"(gptr));
}
#define CP_COMMIT() asm volatile("cp.async.commit_group;" ::: "memory")
#define CP_WAIT(n)  asm volatile("cp.async.wait_group %0;" :: "n"(n) : "memory")

__device__ __forceinline__ void mma_tf32(
    float& d0, float& d1, float& d2, float& d3,
    uint32_t a0, uint32_t a1, uint32_t a2, uint32_t a3,
    uint32_t b0, uint32_t b1)
{
    asm volatile(
        "mma.sync.aligned.m16n8k8.row.col.f32.tf32.tf32.f32 "
        "{%0,%1,%2,%3}, {%4,%5,%6,%7}, {%8,%9}, {%0,%1,%2,%3};"
        : "+f"(d0), "+f"(d1), "+f"(d2), "+f"(d3)
        : "r"(a0), "r"(a1), "r"(a2), "r"(a3), "r"(b0), "r"(b1));
}

// ---------------------------------------------------------------------------
// Launch 1: merged prep (weight transposes + input round/permute)
// ---------------------------------------------------------------------------
#define N8IN 2097152L   // 4096*4096/8
__global__ void prep_kernel(
    const float* __restrict__ Wq, const float* __restrict__ Wk,
    const float* __restrict__ Wv, const float* __restrict__ Wo,
    float* __restrict__ wqT, float* __restrict__ wkT,
    float* __restrict__ wvT, float* __restrict__ woT,
    const float4* __restrict__ qx, const float4* __restrict__ kvx,
    float4* __restrict__ oq, float4* __restrict__ okv)
{
    int z = blockIdx.z;
    int tid = threadIdx.x;
    if (z == 4) {
        long i = ((long)(blockIdx.y * 128 + blockIdx.x)) * 256 + tid;
        const float4* s; float4* d; long j;
        if (i < N8IN) { s = qx; d = oq; j = i; }
        else          { s = kvx; d = okv; j = i - N8IN; }
        float4 v0 = s[j * 2], v1 = s[j * 2 + 1];
        float4 w0, w1;
        w0.x = rndf(v0.x); w0.y = rndf(v1.x); w0.z = rndf(v0.y); w0.w = rndf(v1.y);
        w1.x = rndf(v0.z); w1.y = rndf(v1.z); w1.z = rndf(v0.w); w1.w = rndf(v1.w);
        d[j * 2]     = w0;
        d[j * 2 + 1] = w1;
        return;
    }
    __shared__ float tile[32][33];
    const float* src; float* dst; int rows, cols;
    if (z == 0)      { src = Wq; dst = wqT; rows = 4096; cols = 4096; }
    else if (z == 1) { src = Wk; dst = wkT; rows = 4096; cols = 1024; if (blockIdx.x >= 32) return; }
    else if (z == 2) { src = Wv; dst = wvT; rows = 4096; cols = 1024; if (blockIdx.x >= 32) return; }
    else             { src = Wo; dst = woT; rows = 4096; cols = 4096; }
    int c0 = blockIdx.x * 32, r0 = blockIdx.y * 32;
    int x = tid & 31, y0 = tid >> 5;
    int jb = x & 7;
    int px = (x & ~7) + ((jb < 4) ? 2 * jb : 2 * (jb - 4) + 1);
    #pragma unroll
    for (int y = y0; y < 32; y += 8)
        tile[y][x] = src[(size_t)(r0 + y) * cols + c0 + x];
    __syncthreads();
    #pragma unroll
    for (int y = y0; y < 32; y += 8)
        dst[(size_t)(c0 + y) * rows + r0 + px] = rndf(tile[x][y]);
}

// ---------------------------------------------------------------------------
// tf32 mma.sync GEMM core: 128x128 tile, 256 threads, 2 CTAs/SM,
// double-buffered cp.async, single sync per k-tile.  (R9/R11 proven config)
// ---------------------------------------------------------------------------
#define SA        40
#define STAGE_FLT (2 * 128 * SA)
#define GEMM_SMEM (2 * STAGE_FLT * 4)     // 81920
#define KTILES    (GK / 32)

__device__ __forceinline__ void gemm_core(
    int N, const float* __restrict__ A, const float* __restrict__ BT,
    const float* __restrict__ bias, float* __restrict__ C,
    int m0, int n0, float* sm)
{
    uint32_t sb = smem_to_u32(sm);
    int tid  = threadIdx.x;
    int lane = tid & 31, wid = tid >> 5;
    int wr = wid >> 2, wc = wid & 3;
    int g  = lane >> 2, tg = lane & 3;
    int ldRow = tid >> 3;
    int ldC4  = (tid & 7) * 4;

    float acc[4][4][4];
    #pragma unroll
    for (int i = 0; i < 4; i++)
        #pragma unroll
        for (int j = 0; j < 4; j++)
            #pragma unroll
            for (int k = 0; k < 4; k++) acc[i][j][k] = 0.f;

    auto issue_tile = [&](int kt, int s) {
        const float* Ag = A  + (size_t)(m0) * GK + kt * 32;
        const float* Bg = BT + (size_t)(n0) * GK + kt * 32;
        uint32_t stA = sb + (uint32_t)(s * STAGE_FLT) * 4;
        uint32_t stB = stA + (uint32_t)(128 * SA) * 4;
        #pragma unroll
        for (int i = 0; i < 4; i++) {
            int row = ldRow + 32 * i;
            uint32_t soff = (uint32_t)(row * SA + ldC4) * 4;
            cp_async16(stA + soff, Ag + (size_t)row * GK + ldC4);
            cp_async16(stB + soff, Bg + (size_t)row * GK + ldC4);
        }
    };

    issue_tile(0, 0);
    CP_COMMIT();

    for (int kt = 0; kt < KTILES; kt++) {
        int s = kt & 1;
        CP_WAIT(0);
        __syncthreads();
        if (kt + 1 < KTILES) { issue_tile(kt + 1, s ^ 1); CP_COMMIT(); }

        const float* As = sm + s * STAGE_FLT;
        const float* Bs = As + 128 * SA;

        #pragma unroll
        for (int ks = 0; ks < 4; ks++) {
            int kb = ks * 8 + 2 * tg;
            uint32_t bfr[4][2];
            #pragma unroll
            for (int nt = 0; nt < 4; nt++) {
                float2 lb = *(const float2*)(Bs + (wc * 32 + nt * 8 + g) * SA + kb);
                bfr[nt][0] = __float_as_uint(lb.x);
                bfr[nt][1] = __float_as_uint(lb.y);
            }
            #pragma unroll
            for (int mt = 0; mt < 4; mt++) {
                int ar0 = wr * 64 + mt * 16 + g;
                float2 l0 = *(const float2*)(As + ar0 * SA + kb);
                float2 l1 = *(const float2*)(As + (ar0 + 8) * SA + kb);
                uint32_t a0 = __float_as_uint(l0.x);
                uint32_t a1 = __float_as_uint(l1.x);
                uint32_t a2 = __float_as_uint(l0.y);
                uint32_t a3 = __float_as_uint(l1.y);
                #pragma unroll
                for (int nt = 0; nt < 4; nt++)
                    mma_tf32(acc[mt][nt][0], acc[mt][nt][1], acc[mt][nt][2], acc[mt][nt][3],
                             a0, a1, a2, a3, bfr[nt][0], bfr[nt][1]);
            }
        }
    }

    #pragma unroll
    for (int mt = 0; mt < 4; mt++) {
        int r0 = m0 + wr * 64 + mt * 16 + g;
        #pragma unroll
        for (int nt = 0; nt < 4; nt++) {
            int cc = n0 + wc * 32 + nt * 8 + 2 * tg;
            float2 bv = *(const float2*)(bias + cc);
            float2 o0, o1;
            o0.x = acc[mt][nt][0] + bv.x;
            o0.y = acc[mt][nt][1] + bv.y;
            o1.x = acc[mt][nt][2] + bv.x;
            o1.y = acc[mt][nt][3] + bv.y;
            *(float2*)(C + (size_t)r0 * N + cc)       = o0;
            *(float2*)(C + (size_t)(r0 + 8) * N + cc) = o1;
        }
    }
}

// Launch 2: fused Q+K+V projections (grid.x = 48)
__global__ __launch_bounds__(256, 2) void mma_gemm_qkv(
    const float* __restrict__ Aq, const float* __restrict__ Akv,
    const float* __restrict__ BTq, const float* __restrict__ BTk, const float* __restrict__ BTv,
    const float* __restrict__ bq, const float* __restrict__ bk, const float* __restrict__ bv,
    float* __restrict__ Cq, float* __restrict__ Ck, float* __restrict__ Cv)
{
    extern __shared__ float sm[];
    int bx = blockIdx.x, by = blockIdx.y;
    if (bx < 32)      gemm_core(4096, Aq,  BTq, bq, Cq, by * 128, bx * 128, sm);
    else if (bx < 40) gemm_core(1024, Akv, BTk, bk, Ck, by * 128, (bx - 32) * 128, sm);
    else              gemm_core(1024, Akv, BTv, bv, Cv, by * 128, (bx - 40) * 128, sm);
}

// Launch 5: O projection
__global__ __launch_bounds__(256, 2) void mma_gemm_bias(
    int N, const float* __restrict__ A, const float* __restrict__ BT,
    const float* __restrict__ bias, float* __restrict__ C)
{
    extern __shared__ float sm[];
    gemm_core(N, A, BT, bias, C, blockIdx.y * 128, blockIdx.x * 128, sm);
}

// ---------------------------------------------------------------------------
// Launch 3: MERGED fixup = RoPE(Q,K)+d-permute  AND  V transpose->Vt.
// First PP_BLOCKS blocks do RoPE; remaining 4096 blocks do vtrans.
// ---------------------------------------------------------------------------
#define QROWS (B_*T_*H_)      // 131072
#define KROWS (B_*T_*KVH_)    // 32768
#define PP_BLOCKS ((unsigned)(((long)(QROWS + KROWS) * 8) / 256))   // 5120
#define VT_BLOCKS (64 * 4 * 16)                                     // 4096
#define LOG2_10000_D64 0.20762050593048358f

__global__ __launch_bounds__(256) void fixup_kernel(
    float* __restrict__ Q, float* __restrict__ K,
    const float* __restrict__ V, float* __restrict__ Vt)
{
    int tid = threadIdx.x;
    if (blockIdx.x < PP_BLOCKS) {
        // ---- RoPE(Q,K) + tf32-round + d-pair-permute (in-place safe) ----
        long i = (long)blockIdx.x * 256 + tid;
        float* X; int hshift; long idx;
        if (i < (long)QROWS * 8) { X = Q; hshift = 5; idx = i; }
        else                     { X = K; hshift = 3; idx = i - (long)QROWS * 8; }
        int j0 = (int)(idx & 7);
        long rh = idx >> 3;
        long row = rh >> hshift;
        int t = (int)(row & (T_ - 1));

        float* p = X + rh * HS_ + j0 * 8;
        float lo[8], hi[8], ol[8], oh[8];
        *(float4*)(lo)     = *(const float4*)(p);
        *(float4*)(lo + 4) = *(const float4*)(p + 4);
        *(float4*)(hi)     = *(const float4*)(p + 64);
        *(float4*)(hi + 4) = *(const float4*)(p + 68);
        #pragma unroll
        for (int jj = 0; jj < 8; jj++) {
            int d = j0 * 8 + jj;
            float inv = exp2f(-(float)d * LOG2_10000_D64);
            float ang = (float)t * inv;
            float c = cosf(ang), s = sinf(ang);
            ol[jj] = rndf(lo[jj] * c - hi[jj] * s);
            oh[jj] = rndf(hi[jj] * c + lo[jj] * s);
        }
        float4 w0, w1;
        w0.x = ol[0]; w0.y = ol[4]; w0.z = ol[1]; w0.w = ol[5];
        w1.x = ol[2]; w1.y = ol[6]; w1.z = ol[3]; w1.w = ol[7];
        *(float4*)(p)     = w0;
        *(float4*)(p + 4) = w1;
        w0.x = oh[0]; w0.y = oh[4]; w0.z = oh[1]; w0.w = oh[5];
        w1.x = oh[2]; w1.y = oh[6]; w1.z = oh[3]; w1.w = oh[7];
        *(float4*)(p + 64) = w0;
        *(float4*)(p + 68) = w1;
    } else {
        // ---- V transpose -> Vt[b][kh][d][t], tf32-rounded, t-permuted ----
        __shared__ float tile[32][33];
        int zz = blockIdx.x - PP_BLOCKS;
        int tb = zz & 63;            // T_/32 = 64
        int db = (zz >> 6) & 3;      // HS_/32 = 4
        int z  = zz >> 8;            // b*KVH + kh, 16
        int b = z >> 3, kh = z & 7;
        int t0 = tb * 32, d0 = db * 32;
        int x = tid & 31, y0 = tid >> 5;
        #pragma unroll
        for (int y = y0; y < 32; y += 8)
            tile[y][x] = V[((size_t)(b * T_ + t0 + y) * KVH_ + kh) * HS_ + d0 + x];
        __syncthreads();
        int jb = x & 7;
        int px = (x & ~7) + ((jb < 4) ? 2 * jb : 2 * (jb - 4) + 1);
        #pragma unroll
        for (int y = y0; y < 32; y += 8)
            Vt[((size_t)z * HS_ + d0 + y) * T_ + t0 + px] = rndf(tile[x][y]);
    }
}

// ---------------------------------------------------------------------------
// Launch 4: tensor-core causal flash attention.
// exp2-domain softmax; P via register shuffles; single sync per tile.
// ---------------------------------------------------------------------------
#define KS 136
#define VS 72
#define OFF_KS0 0
#define OFF_KS1 8704
#define OFF_VS0 17408
#define OFF_VS1 26624
#define ATTN_SMEM (35840 * 4)

__global__ __launch_bounds__(256) void attn_mma(
    const float* __restrict__ Q, const float* __restrict__ K,
    const float* __restrict__ Vt, float* __restrict__ Y)
{
    extern __shared__ float sm[];
    uint32_t sb = smem_to_u32(sm);
    int tid = threadIdx.x, lane = tid & 31, w = tid >> 5;
    int g = lane >> 2, tg = lane & 3;
    int qb = gridDim.x - 1 - blockIdx.x;
    int h = blockIdx.y, b = blockIdx.z;
    int kh = h / GROUPS;
    const float scale_l2e = 0.08838834764831845f * 1.4426950408889634f;
    int r0 = qb * 128 + w * 16 + g;

    for (int i = tid; i < 128 * 32; i += 256) {
        int row = i >> 5, c4 = (i & 31) * 4;
        *(float4*)(sm + row * KS + c4) =
            *(const float4*)(Q + (size_t)(b * T_ + qb * 128 + row) * (H_ * HS_) + h * HS_ + c4);
    }
    __syncthreads();
    uint32_t qf[16][4];
    #pragma unroll
    for (int ks = 0; ks < 16; ks++) {
        int kb = ks * 8 + 2 * tg;
        float2 q0 = *(const float2*)(sm + (w * 16 + g)     * KS + kb);
        float2 q1 = *(const float2*)(sm + (w * 16 + g + 8) * KS + kb);
        qf[ks][0] = f2tf32(q0.x * scale_l2e);
        qf[ks][1] = f2tf32(q1.x * scale_l2e);
        qf[ks][2] = f2tf32(q0.y * scale_l2e);
        qf[ks][3] = f2tf32(q1.y * scale_l2e);
    }
    __syncthreads();

    float O[16][4];
    #pragma unroll
    for (int i = 0; i < 16; i++)
        #pragma unroll
        for (int j = 0; j < 4; j++) O[i][j] = 0.f;
    float m0 = -1e30f, m1 = -1e30f, l0 = 0.f, l1 = 0.f;

    int nt = 2 * qb + 2;

    auto issue_kv = [&](int jt, int s) {
        uint32_t kbase = sb + (uint32_t)(s ? OFF_KS1 : OFF_KS0) * 4;
        uint32_t vbase = sb + (uint32_t)(s ? OFF_VS1 : OFF_VS0) * 4;
        const float* Kg  = K + ((size_t)(b * T_ + jt * 64) * KVH_ + kh) * HS_;
        const float* Vg  = Vt + ((size_t)(b * KVH_ + kh) * HS_) * T_ + jt * 64;
        #pragma unroll
        for (int j = 0; j < 8; j++) {
            int ii = tid + 256 * j;
            int krow = ii >> 5, kc4 = (ii & 31) * 4;
            cp_async16(kbase + (uint32_t)(krow * KS + kc4) * 4,
                       Kg + (size_t)krow * (KVH_ * HS_) + kc4);
            int vrow = ii >> 4, vc4 = (ii & 15) * 4;
            cp_async16(vbase + (uint32_t)(vrow * VS + vc4) * 4,
                       Vg + (size_t)vrow * T_ + vc4);
        }
    };

    issue_kv(0, 0);
    CP_COMMIT();

    for (int jt = 0; jt < nt; jt++) {
        int s = jt & 1;
        CP_WAIT(0);
        __syncthreads();
        if (jt + 1 < nt) { issue_kv(jt + 1, s ^ 1); CP_COMMIT(); }

        const float* Ksm = sm + (s ? OFF_KS1 : OFF_KS0);
        const float* Vsm = sm + (s ? OFF_VS1 : OFF_VS0);

        float S[8][4];
        #pragma unroll
        for (int i = 0; i < 8; i++)
            #pragma unroll
            for (int j = 0; j < 4; j++) S[i][j] = 0.f;

        #pragma unroll
        for (int ks = 0; ks < 16; ks++) {
            int kb = ks * 8 + 2 * tg;
            #pragma unroll
            for (int nf = 0; nf < 8; nf++) {
                float2 lb = *(const float2*)(Ksm + (nf * 8 + g) * KS + kb);
                mma_tf32(S[nf][0], S[nf][1], S[nf][2], S[nf][3],
                         qf[ks][0], qf[ks][1], qf[ks][2], qf[ks][3],
                         __float_as_uint(lb.x), __float_as_uint(lb.y));
            }
        }

        if (jt >= 2 * qb) {
            int cb = jt * 64;
            #pragma unroll
            for (int nf = 0; nf < 8; nf++) {
                int c0 = cb + nf * 8 + 2 * tg, c1 = c0 + 1;
                if (c0 > r0)     S[nf][0] = -1e30f;
                if (c1 > r0)     S[nf][1] = -1e30f;
                if (c0 > r0 + 8) S[nf][2] = -1e30f;
                if (c1 > r0 + 8) S[nf][3] = -1e30f;
            }
        }

        float mx0 = -1e30f, mx1 = -1e30f;
        #pragma unroll
        for (int nf = 0; nf < 8; nf++) {
            mx0 = fmaxf(mx0, fmaxf(S[nf][0], S[nf][1]));
            mx1 = fmaxf(mx1, fmaxf(S[nf][2], S[nf][3]));
        }
        mx0 = fmaxf(mx0, __shfl_xor_sync(0xffffffffu, mx0, 1));
        mx0 = fmaxf(mx0, __shfl_xor_sync(0xffffffffu, mx0, 2));
        mx1 = fmaxf(mx1, __shfl_xor_sync(0xffffffffu, mx1, 1));
        mx1 = fmaxf(mx1, __shfl_xor_sync(0xffffffffu, mx1, 2));

        float mn0 = fmaxf(m0, mx0), mn1 = fmaxf(m1, mx1);
        float a0 = exp2f(m0 - mn0), a1 = exp2f(m1 - mn1);
        float s0 = 0.f, s1 = 0.f;
        #pragma unroll
        for (int nf = 0; nf < 8; nf++) {
            S[nf][0] = exp2f(S[nf][0] - mn0);
            S[nf][1] = exp2f(S[nf][1] - mn0);
            S[nf][2] = exp2f(S[nf][2] - mn1);
            S[nf][3] = exp2f(S[nf][3] - mn1);
            s0 += S[nf][0] + S[nf][1];
            s1 += S[nf][2] + S[nf][3];
        }
        s0 += __shfl_xor_sync(0xffffffffu, s0, 1);
        s0 += __shfl_xor_sync(0xffffffffu, s0, 2);
        s1 += __shfl_xor_sync(0xffffffffu, s1, 1);
        s1 += __shfl_xor_sync(0xffffffffu, s1, 2);
        l0 = l0 * a0 + s0; l1 = l1 * a1 + s1;
        m0 = mn0; m1 = mn1;

        #pragma unroll
        for (int nf2 = 0; nf2 < 16; nf2++) {
            O[nf2][0] *= a0; O[nf2][1] *= a0;
            O[nf2][2] *= a1; O[nf2][3] *= a1;
        }

        int src0 = (lane & 28) | (tg >> 1);
        int src1 = src0 + 2;
        #pragma unroll
        for (int kb2 = 0; kb2 < 8; kb2++) {
            float p00 = __shfl_sync(0xffffffffu, S[kb2][0], src0);
            float p01 = __shfl_sync(0xffffffffu, S[kb2][1], src0);
            float p10 = __shfl_sync(0xffffffffu, S[kb2][2], src0);
            float p11 = __shfl_sync(0xffffffffu, S[kb2][3], src0);
            float r00 = __shfl_sync(0xffffffffu, S[kb2][0], src1);
            float r01 = __shfl_sync(0xffffffffu, S[kb2][1], src1);
            float r10 = __shfl_sync(0xffffffffu, S[kb2][2], src1);
            float r11 = __shfl_sync(0xffffffffu, S[kb2][3], src1);
            int odd = tg & 1;
            uint32_t pa0 = f2tf32(odd ? p01 : p00);
            uint32_t pa1 = f2tf32(odd ? p11 : p10);
            uint32_t pa2 = f2tf32(odd ? r01 : r00);
            uint32_t pa3 = f2tf32(odd ? r11 : r10);
            int vb_off = kb2 * 8 + 2 * tg;
            #pragma unroll
            for (int nf2 = 0; nf2 < 16; nf2++) {
                float2 vb = *(const float2*)(Vsm + (nf2 * 8 + g) * VS + vb_off);
                mma_tf32(O[nf2][0], O[nf2][1], O[nf2][2], O[nf2][3],
                         pa0, pa1, pa2, pa3,
                         __float_as_uint(vb.x), __float_as_uint(vb.y));
            }
        }
    }

    float il0 = 1.f / l0, il1 = 1.f / l1;
    size_t base0 = (size_t)(b * T_ + r0) * (H_ * HS_) + h * HS_;
    size_t base1 = base0 + (size_t)8 * (H_ * HS_);
    int pc = (tg < 2) ? 4 * tg : 4 * tg - 7;
    #pragma unroll
    for (int nf2 = 0; nf2 < 16; nf2++) {
        Y[base0 + nf2 * 8 + pc]     = rndf(O[nf2][0] * il0);
        Y[base0 + nf2 * 8 + pc + 2] = rndf(O[nf2][1] * il0);
        Y[base1 + nf2 * 8 + pc]     = rndf(O[nf2][2] * il1);
        Y[base1 + nf2 * 8 + pc + 2] = rndf(O[nf2][3] * il1);
    }
}

// ---------------------------------------------------------------------------
extern "C" void kernel_launch(void* const* d_in, const int* in_sizes, int n_in,
                              void* d_out, int out_size)
{
    const float* q_x  = (const float*)d_in[0];
    const float* kv_x = (const float*)d_in[1];
    const float* Wq   = (const float*)d_in[2];
    const float* bq   = (const float*)d_in[3];
    const float* Wk   = (const float*)d_in[4];
    const float* bk   = (const float*)d_in[5];
    const float* Wv   = (const float*)d_in[6];
    const float* bv   = (const float*)d_in[7];
    const float* Wo   = (const float*)d_in[8];
    const float* bo   = (const float*)d_in[9];
    float* out = (float*)d_out;

    float *qp, *kp, *vp, *vtp, *yp, *wqT, *wkT, *wvT, *woT, *xq, *xkv;
    cudaGetSymbolAddress((void**)&qp, g_Q);
    cudaGetSymbolAddress((void**)&kp, g_K);
    cudaGetSymbolAddress((void**)&vp, g_V);
    cudaGetSymbolAddress((void**)&vtp, g_Vt);
    cudaGetSymbolAddress((void**)&yp, g_Y);
    cudaGetSymbolAddress((void**)&wqT, g_WqT);
    cudaGetSymbolAddress((void**)&wkT, g_WkT);
    cudaGetSymbolAddress((void**)&wvT, g_WvT);
    cudaGetSymbolAddress((void**)&woT, g_WoT);
    cudaGetSymbolAddress((void**)&xq, g_Xq);
    cudaGetSymbolAddress((void**)&xkv, g_Xkv);

    const int M = B_ * T_;

    cudaFuncSetAttribute(mma_gemm_qkv, cudaFuncAttributeMaxDynamicSharedMemorySize, GEMM_SMEM);
    cudaFuncSetAttribute(mma_gemm_bias, cudaFuncAttributeMaxDynamicSharedMemorySize, GEMM_SMEM);
    cudaFuncSetAttribute(attn_mma, cudaFuncAttributeMaxDynamicSharedMemorySize, ATTN_SMEM);

    // 1. merged prep: weight transposes + input rounding/permutation
    prep_kernel<<<dim3(128, 128, 5), 256>>>(Wq, Wk, Wv, Wo, wqT, wkT, wvT, woT,
                                            (const float4*)q_x, (const float4*)kv_x,
                                            (float4*)xq, (float4*)xkv);
    // 2. fused Q+K+V projections
    mma_gemm_qkv<<<dim3(48, M / 128), 256, GEMM_SMEM>>>(xq, xkv, wqT, wkT, wvT,
                                                        bq, bk, bv, qp, kp, vp);
    // 3. merged fixup: RoPE(Q,K) + V transpose
    fixup_kernel<<<PP_BLOCKS + VT_BLOCKS, 256>>>(qp, kp, vp, vtp);
    // 4. attention
    attn_mma<<<dim3(T_ / 128, H_, B_), 256, ATTN_SMEM>>>(qp, kp, vtp, yp);
    // 5. output projection
    mma_gemm_bias<<<dim3(C_ / 128, M / 128), 256, GEMM_SMEM>>>(C_, yp, woT, bo, out);
}

// round 14
// speedup vs baseline: 1.1492x; 1.0003x over previous
#include <cuda_runtime.h>
#include <math.h>
#include <cstdint>

#define B_   2
#define T_   2048
#define C_   4096
#define H_   32
#define KVH_ 8
#define HS_  128
#define GROUPS (H_/KVH_)
#define GK    4096

// ---------------------------------------------------------------------------
// Scratch
// ---------------------------------------------------------------------------
__device__ float g_Q[(size_t)B_*T_*H_*HS_];
__device__ float g_K[(size_t)B_*T_*KVH_*HS_];
__device__ float g_V[(size_t)B_*T_*KVH_*HS_];
__device__ float g_Vt[(size_t)B_*KVH_*HS_*T_];
__device__ float g_Y[(size_t)B_*T_*H_*HS_];
__device__ float g_WqT[(size_t)C_*H_*HS_];
__device__ float g_WkT[(size_t)C_*KVH_*HS_];
__device__ float g_WvT[(size_t)C_*KVH_*HS_];
__device__ float g_WoT[(size_t)H_*HS_*C_];
__device__ float g_Xq[(size_t)B_*T_*C_];
__device__ float g_Xkv[(size_t)B_*T_*C_];

// ---------------------------------------------------------------------------
// Helpers
// ---------------------------------------------------------------------------
__device__ __forceinline__ uint32_t smem_to_u32(const void* p) {
    uint32_t a;
    asm("{ .reg .u64 t; cvta.to.shared.u64 t, %1; cvt.u32.u64 %0, t; }" : "=r"(a) : "l"(p));
    return a;
}
__device__ __forceinline__ uint32_t f2tf32(float x) {
    uint32_t u;
    asm("cvt.rna.tf32.f32 %0, %1;" : "=r"(u) : "f"(x));
    return u;
}
__device__ __forceinline__ float rndf(float x) { return __uint_as_float(f2tf32(x)); }

__device__ __forceinline__ void cp_async16(uint32_t smem_addr, const void* gptr) {
    asm volatile("cp.async.cg.shared.global [%0], [%1], 16;" :: "r"(smem_addr), "l"(gptr));
}
#define CP_COMMIT() asm volatile("cp.async.commit_group;" ::: "memory")
#define CP_WAIT(n)  asm volatile("cp.async.wait_group %0;" :: "n"(n) : "memory")

__device__ __forceinline__ void mma_tf32(
    float& d0, float& d1, float& d2, float& d3,
    uint32_t a0, uint32_t a1, uint32_t a2, uint32_t a3,
    uint32_t b0, uint32_t b1)
{
    asm volatile(
        "mma.sync.aligned.m16n8k8.row.col.f32.tf32.tf32.f32 "
        "{%0,%1,%2,%3}, {%4,%5,%6,%7}, {%8,%9}, {%0,%1,%2,%3};"
        : "+f"(d0), "+f"(d1), "+f"(d2), "+f"(d3)
        : "r"(a0), "r"(a1), "r"(a2), "r"(a3), "r"(b0), "r"(b1));
}

// ---------------------------------------------------------------------------
// Launch 1: merged prep (weight transposes + input round/permute)
// ---------------------------------------------------------------------------
#define N8IN 2097152L
__global__ void prep_kernel(
    const float* __restrict__ Wq, const float* __restrict__ Wk,
    const float* __restrict__ Wv, const float* __restrict__ Wo,
    float* __restrict__ wqT, float* __restrict__ wkT,
    float* __restrict__ wvT, float* __restrict__ woT,
    const float4* __restrict__ qx, const float4* __restrict__ kvx,
    float4* __restrict__ oq, float4* __restrict__ okv)
{
    int z = blockIdx.z;
    int tid = threadIdx.x;
    if (z == 4) {
        long i = ((long)(blockIdx.y * 128 + blockIdx.x)) * 256 + tid;
        const float4* s; float4* d; long j;
        if (i < N8IN) { s = qx; d = oq; j = i; }
        else          { s = kvx; d = okv; j = i - N8IN; }
        float4 v0 = s[j * 2], v1 = s[j * 2 + 1];
        float4 w0, w1;
        w0.x = rndf(v0.x); w0.y = rndf(v1.x); w0.z = rndf(v0.y); w0.w = rndf(v1.y);
        w1.x = rndf(v0.z); w1.y = rndf(v1.z); w1.z = rndf(v0.w); w1.w = rndf(v1.w);
        d[j * 2]     = w0;
        d[j * 2 + 1] = w1;
        return;
    }
    __shared__ float tile[32][33];
    const float* src; float* dst; int rows, cols;
    if (z == 0)      { src = Wq; dst = wqT; rows = 4096; cols = 4096; }
    else if (z == 1) { src = Wk; dst = wkT; rows = 4096; cols = 1024; if (blockIdx.x >= 32) return; }
    else if (z == 2) { src = Wv; dst = wvT; rows = 4096; cols = 1024; if (blockIdx.x >= 32) return; }
    else             { src = Wo; dst = woT; rows = 4096; cols = 4096; }
    int c0 = blockIdx.x * 32, r0 = blockIdx.y * 32;
    int x = tid & 31, y0 = tid >> 5;
    int jb = x & 7;
    int px = (x & ~7) + ((jb < 4) ? 2 * jb : 2 * (jb - 4) + 1);
    #pragma unroll
    for (int y = y0; y < 32; y += 8)
        tile[y][x] = src[(size_t)(r0 + y) * cols + c0 + x];
    __syncthreads();
    #pragma unroll
    for (int y = y0; y < 32; y += 8)
        dst[(size_t)(c0 + y) * rows + r0 + px] = rndf(tile[x][y]);
}

// ---------------------------------------------------------------------------
// tf32 mma.sync GEMM core: 128x128 CTA tile, 128 threads (4 warps of 64x64),
// 2 CTAs/SM, double-buffered cp.async, single sync per k-tile.
// ---------------------------------------------------------------------------
#define SA        40
#define STAGE_FLT (2 * 128 * SA)
#define GEMM_SMEM (2 * STAGE_FLT * 4)     // 81920
#define KTILES    (GK / 32)

__device__ __forceinline__ void gemm_core(
    int N, const float* __restrict__ A, const float* __restrict__ BT,
    const float* __restrict__ bias, float* __restrict__ C,
    int m0, int n0, float* sm)
{
    uint32_t sb = smem_to_u32(sm);
    int tid  = threadIdx.x;
    int lane = tid & 31, wid = tid >> 5;      // 4 warps
    int wr = wid >> 1, wc = wid & 1;          // 2x2 warp grid, 64x64 tiles
    int g  = lane >> 2, tg = lane & 3;
    int ldRow = tid >> 3;                     // 0..15
    int ldC4  = (tid & 7) * 4;

    float acc[4][8][4];
    #pragma unroll
    for (int i = 0; i < 4; i++)
        #pragma unroll
        for (int j = 0; j < 8; j++)
            #pragma unroll
            for (int k = 0; k < 4; k++) acc[i][j][k] = 0.f;

    auto issue_tile = [&](int kt, int s) {
        const float* Ag = A  + (size_t)(m0) * GK + kt * 32;
        const float* Bg = BT + (size_t)(n0) * GK + kt * 32;
        uint32_t stA = sb + (uint32_t)(s * STAGE_FLT) * 4;
        uint32_t stB = stA + (uint32_t)(128 * SA) * 4;
        #pragma unroll
        for (int i = 0; i < 8; i++) {
            int row = ldRow + 16 * i;
            uint32_t soff = (uint32_t)(row * SA + ldC4) * 4;
            cp_async16(stA + soff, Ag + (size_t)row * GK + ldC4);
            cp_async16(stB + soff, Bg + (size_t)row * GK + ldC4);
        }
    };

    issue_tile(0, 0);
    CP_COMMIT();

    for (int kt = 0; kt < KTILES; kt++) {
        int s = kt & 1;
        CP_WAIT(0);
        __syncthreads();
        if (kt + 1 < KTILES) { issue_tile(kt + 1, s ^ 1); CP_COMMIT(); }

        const float* As = sm + s * STAGE_FLT;
        const float* Bs = As + 128 * SA;

        #pragma unroll
        for (int ks = 0; ks < 4; ks++) {
            int kb = ks * 8 + 2 * tg;
            uint32_t bfr[8][2];
            #pragma unroll
            for (int nt = 0; nt < 8; nt++) {
                float2 lb = *(const float2*)(Bs + (wc * 64 + nt * 8 + g) * SA + kb);
                bfr[nt][0] = __float_as_uint(lb.x);
                bfr[nt][1] = __float_as_uint(lb.y);
            }
            #pragma unroll
            for (int mt = 0; mt < 4; mt++) {
                int ar0 = wr * 64 + mt * 16 + g;
                float2 l0 = *(const float2*)(As + ar0 * SA + kb);
                float2 l1 = *(const float2*)(As + (ar0 + 8) * SA + kb);
                uint32_t a0 = __float_as_uint(l0.x);
                uint32_t a1 = __float_as_uint(l1.x);
                uint32_t a2 = __float_as_uint(l0.y);
                uint32_t a3 = __float_as_uint(l1.y);
                #pragma unroll
                for (int nt = 0; nt < 8; nt++)
                    mma_tf32(acc[mt][nt][0], acc[mt][nt][1], acc[mt][nt][2], acc[mt][nt][3],
                             a0, a1, a2, a3, bfr[nt][0], bfr[nt][1]);
            }
        }
    }

    #pragma unroll
    for (int mt = 0; mt < 4; mt++) {
        int r0 = m0 + wr * 64 + mt * 16 + g;
        #pragma unroll
        for (int nt = 0; nt < 8; nt++) {
            int cc = n0 + wc * 64 + nt * 8 + 2 * tg;
            float2 bv = *(const float2*)(bias + cc);
            float2 o0, o1;
            o0.x = acc[mt][nt][0] + bv.x;
            o0.y = acc[mt][nt][1] + bv.y;
            o1.x = acc[mt][nt][2] + bv.x;
            o1.y = acc[mt][nt][3] + bv.y;
            *(float2*)(C + (size_t)r0 * N + cc)       = o0;
            *(float2*)(C + (size_t)(r0 + 8) * N + cc) = o1;
        }
    }
}

// Launch 2: fused Q+K+V projections (grid.x = 48), 128 threads
__global__ __launch_bounds__(128, 2) void mma_gemm_qkv(
    const float* __restrict__ Aq, const float* __restrict__ Akv,
    const float* __restrict__ BTq, const float* __restrict__ BTk, const float* __restrict__ BTv,
    const float* __restrict__ bq, const float* __restrict__ bk, const float* __restrict__ bv,
    float* __restrict__ Cq, float* __restrict__ Ck, float* __restrict__ Cv)
{
    extern __shared__ float sm[];
    int bx = blockIdx.x, by = blockIdx.y;
    if (bx < 32)      gemm_core(4096, Aq,  BTq, bq, Cq, by * 128, bx * 128, sm);
    else if (bx < 40) gemm_core(1024, Akv, BTk, bk, Ck, by * 128, (bx - 32) * 128, sm);
    else              gemm_core(1024, Akv, BTv, bv, Cv, by * 128, (bx - 40) * 128, sm);
}

// Launch 5: O projection, 128 threads
__global__ __launch_bounds__(128, 2) void mma_gemm_bias(
    int N, const float* __restrict__ A, const float* __restrict__ BT,
    const float* __restrict__ bias, float* __restrict__ C)
{
    extern __shared__ float sm[];
    gemm_core(N, A, BT, bias, C, blockIdx.y * 128, blockIdx.x * 128, sm);
}

// ---------------------------------------------------------------------------
// Launch 3: MERGED fixup = RoPE(Q,K)+d-permute AND V transpose->Vt.
// ---------------------------------------------------------------------------
#define QROWS (B_*T_*H_)
#define KROWS (B_*T_*KVH_)
#define PP_BLOCKS ((unsigned)(((long)(QROWS + KROWS) * 8) / 256))   // 5120
#define VT_BLOCKS (64 * 4 * 16)                                     // 4096
#define LOG2_10000_D64 0.20762050593048358f

__global__ __launch_bounds__(256) void fixup_kernel(
    float* __restrict__ Q, float* __restrict__ K,
    const float* __restrict__ V, float* __restrict__ Vt)
{
    int tid = threadIdx.x;
    if (blockIdx.x < PP_BLOCKS) {
        long i = (long)blockIdx.x * 256 + tid;
        float* X; int hshift; long idx;
        if (i < (long)QROWS * 8) { X = Q; hshift = 5; idx = i; }
        else                     { X = K; hshift = 3; idx = i - (long)QROWS * 8; }
        int j0 = (int)(idx & 7);
        long rh = idx >> 3;
        long row = rh >> hshift;
        int t = (int)(row & (T_ - 1));

        float* p = X + rh * HS_ + j0 * 8;
        float lo[8], hi[8], ol[8], oh[8];
        *(float4*)(lo)     = *(const float4*)(p);
        *(float4*)(lo + 4) = *(const float4*)(p + 4);
        *(float4*)(hi)     = *(const float4*)(p + 64);
        *(float4*)(hi + 4) = *(const float4*)(p + 68);
        #pragma unroll
        for (int jj = 0; jj < 8; jj++) {
            int d = j0 * 8 + jj;
            float inv = exp2f(-(float)d * LOG2_10000_D64);
            float ang = (float)t * inv;
            float c = cosf(ang), s = sinf(ang);
            ol[jj] = rndf(lo[jj] * c - hi[jj] * s);
            oh[jj] = rndf(hi[jj] * c + lo[jj] * s);
        }
        float4 w0, w1;
        w0.x = ol[0]; w0.y = ol[4]; w0.z = ol[1]; w0.w = ol[5];
        w1.x = ol[2]; w1.y = ol[6]; w1.z = ol[3]; w1.w = ol[7];
        *(float4*)(p)     = w0;
        *(float4*)(p + 4) = w1;
        w0.x = oh[0]; w0.y = oh[4]; w0.z = oh[1]; w0.w = oh[5];
        w1.x = oh[2]; w1.y = oh[6]; w1.z = oh[3]; w1.w = oh[7];
        *(float4*)(p + 64) = w0;
        *(float4*)(p + 68) = w1;
    } else {
        __shared__ float tile[32][33];
        int zz = blockIdx.x - PP_BLOCKS;
        int tb = zz & 63;
        int db = (zz >> 6) & 3;
        int z  = zz >> 8;
        int b = z >> 3, kh = z & 7;
        int t0 = tb * 32, d0 = db * 32;
        int x = tid & 31, y0 = tid >> 5;
        #pragma unroll
        for (int y = y0; y < 32; y += 8)
            tile[y][x] = V[((size_t)(b * T_ + t0 + y) * KVH_ + kh) * HS_ + d0 + x];
        __syncthreads();
        int jb = x & 7;
        int px = (x & ~7) + ((jb < 4) ? 2 * jb : 2 * (jb - 4) + 1);
        #pragma unroll
        for (int y = y0; y < 32; y += 8)
            Vt[((size_t)z * HS_ + d0 + y) * T_ + t0 + px] = rndf(tile[x][y]);
    }
}

// ---------------------------------------------------------------------------
// Launch 4: tensor-core causal flash attention (unchanged from R13).
// ---------------------------------------------------------------------------
#define KS 136
#define VS 72
#define OFF_KS0 0
#define OFF_KS1 8704
#define OFF_VS0 17408
#define OFF_VS1 26624
#define ATTN_SMEM (35840 * 4)

__global__ __launch_bounds__(256) void attn_mma(
    const float* __restrict__ Q, const float* __restrict__ K,
    const float* __restrict__ Vt, float* __restrict__ Y)
{
    extern __shared__ float sm[];
    uint32_t sb = smem_to_u32(sm);
    int tid = threadIdx.x, lane = tid & 31, w = tid >> 5;
    int g = lane >> 2, tg = lane & 3;
    int qb = gridDim.x - 1 - blockIdx.x;
    int h = blockIdx.y, b = blockIdx.z;
    int kh = h / GROUPS;
    const float scale_l2e = 0.08838834764831845f * 1.4426950408889634f;
    int r0 = qb * 128 + w * 16 + g;

    for (int i = tid; i < 128 * 32; i += 256) {
        int row = i >> 5, c4 = (i & 31) * 4;
        *(float4*)(sm + row * KS + c4) =
            *(const float4*)(Q + (size_t)(b * T_ + qb * 128 + row) * (H_ * HS_) + h * HS_ + c4);
    }
    __syncthreads();
    uint32_t qf[16][4];
    #pragma unroll
    for (int ks = 0; ks < 16; ks++) {
        int kb = ks * 8 + 2 * tg;
        float2 q0 = *(const float2*)(sm + (w * 16 + g)     * KS + kb);
        float2 q1 = *(const float2*)(sm + (w * 16 + g + 8) * KS + kb);
        qf[ks][0] = f2tf32(q0.x * scale_l2e);
        qf[ks][1] = f2tf32(q1.x * scale_l2e);
        qf[ks][2] = f2tf32(q0.y * scale_l2e);
        qf[ks][3] = f2tf32(q1.y * scale_l2e);
    }
    __syncthreads();

    float O[16][4];
    #pragma unroll
    for (int i = 0; i < 16; i++)
        #pragma unroll
        for (int j = 0; j < 4; j++) O[i][j] = 0.f;
    float m0 = -1e30f, m1 = -1e30f, l0 = 0.f, l1 = 0.f;

    int nt = 2 * qb + 2;

    auto issue_kv = [&](int jt, int s) {
        uint32_t kbase = sb + (uint32_t)(s ? OFF_KS1 : OFF_KS0) * 4;
        uint32_t vbase = sb + (uint32_t)(s ? OFF_VS1 : OFF_VS0) * 4;
        const float* Kg  = K + ((size_t)(b * T_ + jt * 64) * KVH_ + kh) * HS_;
        const float* Vg  = Vt + ((size_t)(b * KVH_ + kh) * HS_) * T_ + jt * 64;
        #pragma unroll
        for (int j = 0; j < 8; j++) {
            int ii = tid + 256 * j;
            int krow = ii >> 5, kc4 = (ii & 31) * 4;
            cp_async16(kbase + (uint32_t)(krow * KS + kc4) * 4,
                       Kg + (size_t)krow * (KVH_ * HS_) + kc4);
            int vrow = ii >> 4, vc4 = (ii & 15) * 4;
            cp_async16(vbase + (uint32_t)(vrow * VS + vc4) * 4,
                       Vg + (size_t)vrow * T_ + vc4);
        }
    };

    issue_kv(0, 0);
    CP_COMMIT();

    for (int jt = 0; jt < nt; jt++) {
        int s = jt & 1;
        CP_WAIT(0);
        __syncthreads();
        if (jt + 1 < nt) { issue_kv(jt + 1, s ^ 1); CP_COMMIT(); }

        const float* Ksm = sm + (s ? OFF_KS1 : OFF_KS0);
        const float* Vsm = sm + (s ? OFF_VS1 : OFF_VS0);

        float S[8][4];
        #pragma unroll
        for (int i = 0; i < 8; i++)
            #pragma unroll
            for (int j = 0; j < 4; j++) S[i][j] = 0.f;

        #pragma unroll
        for (int ks = 0; ks < 16; ks++) {
            int kb = ks * 8 + 2 * tg;
            #pragma unroll
            for (int nf = 0; nf < 8; nf++) {
                float2 lb = *(const float2*)(Ksm + (nf * 8 + g) * KS + kb);
                mma_tf32(S[nf][0], S[nf][1], S[nf][2], S[nf][3],
                         qf[ks][0], qf[ks][1], qf[ks][2], qf[ks][3],
                         __float_as_uint(lb.x), __float_as_uint(lb.y));
            }
        }

        if (jt >= 2 * qb) {
            int cb = jt * 64;
            #pragma unroll
            for (int nf = 0; nf < 8; nf++) {
                int c0 = cb + nf * 8 + 2 * tg, c1 = c0 + 1;
                if (c0 > r0)     S[nf][0] = -1e30f;
                if (c1 > r0)     S[nf][1] = -1e30f;
                if (c0 > r0 + 8) S[nf][2] = -1e30f;
                if (c1 > r0 + 8) S[nf][3] = -1e30f;
            }
        }

        float mx0 = -1e30f, mx1 = -1e30f;
        #pragma unroll
        for (int nf = 0; nf < 8; nf++) {
            mx0 = fmaxf(mx0, fmaxf(S[nf][0], S[nf][1]));
            mx1 = fmaxf(mx1, fmaxf(S[nf][2], S[nf][3]));
        }
        mx0 = fmaxf(mx0, __shfl_xor_sync(0xffffffffu, mx0, 1));
        mx0 = fmaxf(mx0, __shfl_xor_sync(0xffffffffu, mx0, 2));
        mx1 = fmaxf(mx1, __shfl_xor_sync(0xffffffffu, mx1, 1));
        mx1 = fmaxf(mx1, __shfl_xor_sync(0xffffffffu, mx1, 2));

        float mn0 = fmaxf(m0, mx0), mn1 = fmaxf(m1, mx1);
        float a0 = exp2f(m0 - mn0), a1 = exp2f(m1 - mn1);
        float s0 = 0.f, s1 = 0.f;
        #pragma unroll
        for (int nf = 0; nf < 8; nf++) {
            S[nf][0] = exp2f(S[nf][0] - mn0);
            S[nf][1] = exp2f(S[nf][1] - mn0);
            S[nf][2] = exp2f(S[nf][2] - mn1);
            S[nf][3] = exp2f(S[nf][3] - mn1);
            s0 += S[nf][0] + S[nf][1];
            s1 += S[nf][2] + S[nf][3];
        }
        s0 += __shfl_xor_sync(0xffffffffu, s0, 1);
        s0 += __shfl_xor_sync(0xffffffffu, s0, 2);
        s1 += __shfl_xor_sync(0xffffffffu, s1, 1);
        s1 += __shfl_xor_sync(0xffffffffu, s1, 2);
        l0 = l0 * a0 + s0; l1 = l1 * a1 + s1;
        m0 = mn0; m1 = mn1;

        #pragma unroll
        for (int nf2 = 0; nf2 < 16; nf2++) {
            O[nf2][0] *= a0; O[nf2][1] *= a0;
            O[nf2][2] *= a1; O[nf2][3] *= a1;
        }

        int src0 = (lane & 28) | (tg >> 1);
        int src1 = src0 + 2;
        #pragma unroll
        for (int kb2 = 0; kb2 < 8; kb2++) {
            float p00 = __shfl_sync(0xffffffffu, S[kb2][0], src0);
            float p01 = __shfl_sync(0xffffffffu, S[kb2][1], src0);
            float p10 = __shfl_sync(0xffffffffu, S[kb2][2], src0);
            float p11 = __shfl_sync(0xffffffffu, S[kb2][3], src0);
            float r00 = __shfl_sync(0xffffffffu, S[kb2][0], src1);
            float r01 = __shfl_sync(0xffffffffu, S[kb2][1], src1);
            float r10 = __shfl_sync(0xffffffffu, S[kb2][2], src1);
            float r11 = __shfl_sync(0xffffffffu, S[kb2][3], src1);
            int odd = tg & 1;
            uint32_t pa0 = f2tf32(odd ? p01 : p00);
            uint32_t pa1 = f2tf32(odd ? p11 : p10);
            uint32_t pa2 = f2tf32(odd ? r01 : r00);
            uint32_t pa3 = f2tf32(odd ? r11 : r10);
            int vb_off = kb2 * 8 + 2 * tg;
            #pragma unroll
            for (int nf2 = 0; nf2 < 16; nf2++) {
                float2 vb = *(const float2*)(Vsm + (nf2 * 8 + g) * VS + vb_off);
                mma_tf32(O[nf2][0], O[nf2][1], O[nf2][2], O[nf2][3],
                         pa0, pa1, pa2, pa3,
                         __float_as_uint(vb.x), __float_as_uint(vb.y));
            }
        }
    }

    float il0 = 1.f / l0, il1 = 1.f / l1;
    size_t base0 = (size_t)(b * T_ + r0) * (H_ * HS_) + h * HS_;
    size_t base1 = base0 + (size_t)8 * (H_ * HS_);
    int pc = (tg < 2) ? 4 * tg : 4 * tg - 7;
    #pragma unroll
    for (int nf2 = 0; nf2 < 16; nf2++) {
        Y[base0 + nf2 * 8 + pc]     = rndf(O[nf2][0] * il0);
        Y[base0 + nf2 * 8 + pc + 2] = rndf(O[nf2][1] * il0);
        Y[base1 + nf2 * 8 + pc]     = rndf(O[nf2][2] * il1);
        Y[base1 + nf2 * 8 + pc + 2] = rndf(O[nf2][3] * il1);
    }
}

// ---------------------------------------------------------------------------
extern "C" void kernel_launch(void* const* d_in, const int* in_sizes, int n_in,
                              void* d_out, int out_size)
{
    const float* q_x  = (const float*)d_in[0];
    const float* kv_x = (const float*)d_in[1];
    const float* Wq   = (const float*)d_in[2];
    const float* bq   = (const float*)d_in[3];
    const float* Wk   = (const float*)d_in[4];
    const float* bk   = (const float*)d_in[5];
    const float* Wv   = (const float*)d_in[6];
    const float* bv   = (const float*)d_in[7];
    const float* Wo   = (const float*)d_in[8];
    const float* bo   = (const float*)d_in[9];
    float* out = (float*)d_out;

    float *qp, *kp, *vp, *vtp, *yp, *wqT, *wkT, *wvT, *woT, *xq, *xkv;
    cudaGetSymbolAddress((void**)&qp, g_Q);
    cudaGetSymbolAddress((void**)&kp, g_K);
    cudaGetSymbolAddress((void**)&vp, g_V);
    cudaGetSymbolAddress((void**)&vtp, g_Vt);
    cudaGetSymbolAddress((void**)&yp, g_Y);
    cudaGetSymbolAddress((void**)&wqT, g_WqT);
    cudaGetSymbolAddress((void**)&wkT, g_WkT);
    cudaGetSymbolAddress((void**)&wvT, g_WvT);
    cudaGetSymbolAddress((void**)&woT, g_WoT);
    cudaGetSymbolAddress((void**)&xq, g_Xq);
    cudaGetSymbolAddress((void**)&xkv, g_Xkv);

    const int M = B_ * T_;

    cudaFuncSetAttribute(mma_gemm_qkv, cudaFuncAttributeMaxDynamicSharedMemorySize, GEMM_SMEM);
    cudaFuncSetAttribute(mma_gemm_bias, cudaFuncAttributeMaxDynamicSharedMemorySize, GEMM_SMEM);
    cudaFuncSetAttribute(attn_mma, cudaFuncAttributeMaxDynamicSharedMemorySize, ATTN_SMEM);

    prep_kernel<<<dim3(128, 128, 5), 256>>>(Wq, Wk, Wv, Wo, wqT, wkT, wvT, woT,
                                            (const float4*)q_x, (const float4*)kv_x,
                                            (float4*)xq, (float4*)xkv);
    mma_gemm_qkv<<<dim3(48, M / 128), 128, GEMM_SMEM>>>(xq, xkv, wqT, wkT, wvT,
                                                        bq, bk, bv, qp, kp, vp);
    fixup_kernel<<<PP_BLOCKS + VT_BLOCKS, 256>>>(qp, kp, vp, vtp);
    attn_mma<<<dim3(T_ / 128, H_, B_), 256, ATTN_SMEM>>>(qp, kp, vtp, yp);
    mma_gemm_bias<<<dim3(C_ / 128, M / 128), 128, GEMM_SMEM>>>(C_, yp, woT, bo, out);
}